// round 4
// baseline (speedup 1.0000x reference)
#include <cuda_runtime.h>
#include <cstdint>

// FasterPConv via portable mma.sync m16n8k8 tf32 (3xTF32 precision).
// B=2, N=80000, K=16, C=32, H=4, M=8.
// Per point: out[32c x 8m] = gf^T(32x16) * w(16x8), one warp per point.
// gf[k][c] = feat[b, idx[k], c] * guid[k, c>>3].

#define NPERB 80000
#define FULLMASK 0xffffffffu

__device__ __forceinline__ uint32_t tf32_hi(float v) {
    uint32_t u;
    asm("cvt.rna.tf32.f32 %0, %1;" : "=r"(u) : "f"(v));
    return u;
}

__device__ __forceinline__ void mma8(float d[4], const uint32_t a[4],
                                     uint32_t b0, uint32_t b1) {
    asm volatile(
        "mma.sync.aligned.m16n8k8.row.col.f32.tf32.tf32.f32 "
        "{%0,%1,%2,%3}, {%4,%5,%6,%7}, {%8,%9}, {%0,%1,%2,%3};"
        : "+f"(d[0]), "+f"(d[1]), "+f"(d[2]), "+f"(d[3])
        : "r"(a[0]), "r"(a[1]), "r"(a[2]), "r"(a[3]), "r"(b0), "r"(b1));
}

__global__ void __launch_bounds__(256)
pconv_hmma(const float* __restrict__ feat, const int* __restrict__ inds,
           const float* __restrict__ guid, const float* __restrict__ wn,
           float* __restrict__ out) {
    // Per-warp staging. Row stride 40 words (40 mod 32 = 8): bank = (8k + c) & 31,
    // bijective over every fragment's 32 lanes -> conflict-free STS and LDS.
    // Reused (stride 36) for the D transpose before the coalesced store.
    __shared__ float s_gf[8][16 * 40];

    const int warp = threadIdx.x >> 5;
    const int lane = threadIdx.x & 31;
    const int point = blockIdx.x * 8 + warp;       // grid covers 160000 exactly
    float* sg = s_gf[warp];

    // ---- neighbor indices (16 ints, lanes 0..15) ----
    int myidx = 0;
    if (lane < 16) myidx = __ldg(inds + point * 16 + lane);

    // ---- guidance, coalesced: lane j holds guid[point*64 + j] ----
    const float g0 = __ldg(guid + point * 64 + lane);
    const float g1 = __ldg(guid + point * 64 + 32 + lane);
    const int h = lane >> 3;                        // head of this lane's channel

    const float* fb = feat + ((point >= NPERB) ? NPERB * 32 : 0);

    // ---- gather + guidance multiply + stage gf[k][c] ----
    #pragma unroll
    for (int k = 0; k < 16; k++) {
        const int ik = __shfl_sync(FULLMASK, myidx, k);
        const float fv = __ldg(fb + ik * 32 + lane);
        const float gv = (k < 8) ? __shfl_sync(FULLMASK, g0, k * 4 + h)
                                 : __shfl_sync(FULLMASK, g1, (k - 8) * 4 + h);
        sg[k * 40 + lane] = fv * gv;
    }
    __syncwarp();

    // ---- B fragments (w[k][m]) direct from GMEM ----
    // b(q,j): k = (lane&3) + 4j + 8q, m = lane>>2.
    // Word index 8*(lane&3) + (lane>>2) + 32j + 64q: each LDG covers one
    // permuted-but-contiguous 128B line -> coalesced.
    const float* wp = wn + (size_t)point * 128;
    const int widx = 8 * (lane & 3) + (lane >> 2);
    uint32_t Bhi[2][2], Blo[2][2];
    #pragma unroll
    for (int q = 0; q < 2; q++)
        #pragma unroll
        for (int j = 0; j < 2; j++) {
            const float v = __ldg(wp + widx + 32 * j + 64 * q);
            Bhi[q][j] = tf32_hi(v);
            Blo[q][j] = tf32_hi(v - __uint_as_float(Bhi[q][j]));
        }

    float d[2][4];
    #pragma unroll
    for (int t = 0; t < 2; t++)
        #pragma unroll
        for (int i = 0; i < 4; i++) d[t][i] = 0.0f;

    // ---- 2 M-tiles x 2 K-halves, 3xTF32 each ----
    #pragma unroll
    for (int t = 0; t < 2; t++) {
        #pragma unroll
        for (int q = 0; q < 2; q++) {
            uint32_t Ahi[4], Alo[4];
            #pragma unroll
            for (int i = 0; i < 4; i++) {
                const int k = (lane & 3) + 4 * (i >> 1) + 8 * q;
                const int c = (lane >> 2) + 8 * (i & 1) + 16 * t;
                const float v = sg[k * 40 + c];
                Ahi[i] = tf32_hi(v);
                Alo[i] = tf32_hi(v - __uint_as_float(Ahi[i]));
            }
            mma8(d[t], Ahi, Bhi[q][0], Bhi[q][1]);   // hi*hi
            mma8(d[t], Alo, Bhi[q][0], Bhi[q][1]);   // lo*hi
            mma8(d[t], Ahi, Blo[q][0], Blo[q][1]);   // hi*lo
        }
    }
    __syncwarp();   // all A-frag reads complete before sg is overwritten

    // ---- D -> smem transpose (stride 36: bank = (4m + c)&31, conflict-free) ----
    // d[t][i]: m = (lane&3)*2 + (i&1), c = (lane>>2) + 8*(i>>1) + 16*t.
    #pragma unroll
    for (int t = 0; t < 2; t++)
        #pragma unroll
        for (int i = 0; i < 4; i++) {
            const int m = (lane & 3) * 2 + (i & 1);
            const int c = (lane >> 2) + 8 * (i >> 1) + 16 * t;
            sg[m * 36 + c] = d[t][i];
        }
    __syncwarp();

    // ---- coalesced store: out[point, m*32 + c] ----
    float* op = out + (size_t)point * 256;
    #pragma unroll
    for (int m = 0; m < 8; m++)
        op[m * 32 + lane] = sg[m * 36 + lane];
}

extern "C" void kernel_launch(void* const* d_in, const int* in_sizes, int n_in,
                              void* d_out, int out_size) {
    const float* feat = (const float*)d_in[0];   // [B,N,C]
    const int*   inds = (const int*)  d_in[1];   // [B,N,K]
    const float* guid = (const float*)d_in[2];   // [B,N,K,H]
    const float* wn   = (const float*)d_in[3];   // [B,N,K,M]
    float* out = (float*)d_out;                  // [B,N,M*C]

    pconv_hmma<<<20000, 256>>>(feat, inds, guid, wn, out);
}

// round 6
// speedup vs baseline: 1.0003x; 1.0003x over previous
#include <cuda_runtime.h>
#include <cstdint>

// FasterPConv via portable mma.sync m16n8k8 tf32 (3xTF32 precision).
// B=2, N=80000, K=16, C=32, H=4, M=8.
// Per point: out[32c x 8m] = gf^T(32x16) * w(16x8), one warp per point.
// gf[k][c] = feat[b, idx[k], c] * guid[k, c>>3].

#define NPERB 80000
#define FULLMASK 0xffffffffu

__device__ __forceinline__ uint32_t tf32_hi(float v) {
    uint32_t u;
    asm("cvt.rna.tf32.f32 %0, %1;" : "=r"(u) : "f"(v));
    return u;
}

__device__ __forceinline__ void mma8(float d[4], const uint32_t a[4],
                                     uint32_t b0, uint32_t b1) {
    asm volatile(
        "mma.sync.aligned.m16n8k8.row.col.f32.tf32.tf32.f32 "
        "{%0,%1,%2,%3}, {%4,%5,%6,%7}, {%8,%9}, {%0,%1,%2,%3};"
        : "+f"(d[0]), "+f"(d[1]), "+f"(d[2]), "+f"(d[3])
        : "r"(a[0]), "r"(a[1]), "r"(a[2]), "r"(a[3]), "r"(b0), "r"(b1));
}

__global__ void __launch_bounds__(256)
pconv_hmma(const float* __restrict__ feat, const int* __restrict__ inds,
           const float* __restrict__ guid, const float* __restrict__ wn,
           float* __restrict__ out) {
    // Per-warp staging. Row stride 40 words (40 mod 32 = 8): bank = (8k + c) & 31,
    // bijective over every fragment's 32 lanes -> conflict-free STS and LDS.
    // Reused (stride 36) for the D transpose before the coalesced store.
    __shared__ float s_gf[8][16 * 40];

    const int warp = threadIdx.x >> 5;
    const int lane = threadIdx.x & 31;
    const int point = blockIdx.x * 8 + warp;       // grid covers 160000 exactly
    float* sg = s_gf[warp];

    // ---- neighbor indices (16 ints, lanes 0..15) ----
    int myidx = 0;
    if (lane < 16) myidx = __ldg(inds + point * 16 + lane);

    // ---- B operand loads issued early (raises MLP; values used after gather) ----
    // b(q,j): k = (lane&3) + 4j + 8q, m = lane>>2.
    // Word index 8*(lane&3) + (lane>>2) + 32j + 64q: each LDG covers one
    // permuted-but-contiguous 128B line -> coalesced.
    const float* wp = wn + (size_t)point * 128;
    const int widx = 8 * (lane & 3) + (lane >> 2);
    float wraw[2][2];
    #pragma unroll
    for (int q = 0; q < 2; q++)
        #pragma unroll
        for (int j = 0; j < 2; j++)
            wraw[q][j] = __ldg(wp + widx + 32 * j + 64 * q);

    // ---- guidance, coalesced: lane j holds guid[point*64 + j] ----
    const float g0 = __ldg(guid + point * 64 + lane);
    const float g1 = __ldg(guid + point * 64 + 32 + lane);
    const int h = lane >> 3;                        // head of this lane's channel

    const float* fb = feat + ((point >= NPERB) ? NPERB * 32 : 0);

    // ---- gather + guidance multiply + stage gf[k][c] ----
    #pragma unroll
    for (int k = 0; k < 16; k++) {
        const int ik = __shfl_sync(FULLMASK, myidx, k);
        const float fv = __ldg(fb + ik * 32 + lane);
        const float gv = (k < 8) ? __shfl_sync(FULLMASK, g0, k * 4 + h)
                                 : __shfl_sync(FULLMASK, g1, (k - 8) * 4 + h);
        sg[k * 40 + lane] = fv * gv;
    }
    __syncwarp();

    // ---- split B into tf32 hi/lo fragments ----
    uint32_t Bhi[2][2], Blo[2][2];
    #pragma unroll
    for (int q = 0; q < 2; q++)
        #pragma unroll
        for (int j = 0; j < 2; j++) {
            Bhi[q][j] = tf32_hi(wraw[q][j]);
            Blo[q][j] = tf32_hi(wraw[q][j] - __uint_as_float(Bhi[q][j]));
        }

    float d[2][4];
    #pragma unroll
    for (int t = 0; t < 2; t++)
        #pragma unroll
        for (int i = 0; i < 4; i++) d[t][i] = 0.0f;

    // ---- 2 M-tiles x 2 K-halves, 3xTF32 each ----
    #pragma unroll
    for (int t = 0; t < 2; t++) {
        #pragma unroll
        for (int q = 0; q < 2; q++) {
            uint32_t Ahi[4], Alo[4];
            #pragma unroll
            for (int i = 0; i < 4; i++) {
                const int k = (lane & 3) + 4 * (i >> 1) + 8 * q;
                const int c = (lane >> 2) + 8 * (i & 1) + 16 * t;
                const float v = sg[k * 40 + c];
                Ahi[i] = tf32_hi(v);
                Alo[i] = tf32_hi(v - __uint_as_float(Ahi[i]));
            }
            mma8(d[t], Ahi, Bhi[q][0], Bhi[q][1]);   // hi*hi
            mma8(d[t], Alo, Bhi[q][0], Bhi[q][1]);   // lo*hi
            mma8(d[t], Ahi, Blo[q][0], Blo[q][1]);   // hi*lo
        }
    }
    __syncwarp();   // all A-frag reads complete before sg is overwritten

    // ---- D -> smem transpose (stride 36: bank = (4m + c)&31, conflict-free) ----
    // d[t][i]: m = (lane&3)*2 + (i&1), c = (lane>>2) + 8*(i>>1) + 16*t.
    #pragma unroll
    for (int t = 0; t < 2; t++)
        #pragma unroll
        for (int i = 0; i < 4; i++) {
            const int m = (lane & 3) * 2 + (i & 1);
            const int c = (lane >> 2) + 8 * (i >> 1) + 16 * t;
            sg[m * 36 + c] = d[t][i];
        }
    __syncwarp();

    // ---- coalesced store: out[point, m*32 + c] ----
    float* op = out + (size_t)point * 256;
    #pragma unroll
    for (int m = 0; m < 8; m++)
        op[m * 32 + lane] = sg[m * 36 + lane];
}

extern "C" void kernel_launch(void* const* d_in, const int* in_sizes, int n_in,
                              void* d_out, int out_size) {
    const float* feat = (const float*)d_in[0];   // [B,N,C]
    const int*   inds = (const int*)  d_in[1];   // [B,N,K]
    const float* guid = (const float*)d_in[2];   // [B,N,K,H]
    const float* wn   = (const float*)d_in[3];   // [B,N,K,M]
    float* out = (float*)d_out;                  // [B,N,M*C]

    pconv_hmma<<<20000, 256>>>(feat, inds, guid, wn, out);
}

// round 7
// speedup vs baseline: 1.0685x; 1.0682x over previous
#include <cuda_runtime.h>
#include <cstdint>

// FasterPConv via portable mma.sync m16n8k8 tf32, single-pass tf32 precision.
// B=2, N=80000, K=16, C=32, H=4, M=8.
// Per point: out[32c x 8m] = gf^T(32x16) * w(16x8), one warp per point.
// gf[k][c] = feat[b, idx[k], c] * guid[k, c>>3], rounded to tf32 at gather time.

#define NPERB 80000
#define FULLMASK 0xffffffffu

__device__ __forceinline__ uint32_t tf32_rn(float v) {
    uint32_t u;
    asm("cvt.rna.tf32.f32 %0, %1;" : "=r"(u) : "f"(v));
    return u;
}

__device__ __forceinline__ void mma8(float d[4], const uint32_t a[4],
                                     uint32_t b0, uint32_t b1) {
    asm volatile(
        "mma.sync.aligned.m16n8k8.row.col.f32.tf32.tf32.f32 "
        "{%0,%1,%2,%3}, {%4,%5,%6,%7}, {%8,%9}, {%0,%1,%2,%3};"
        : "+f"(d[0]), "+f"(d[1]), "+f"(d[2]), "+f"(d[3])
        : "r"(a[0]), "r"(a[1]), "r"(a[2]), "r"(a[3]), "r"(b0), "r"(b1));
}

__global__ void __launch_bounds__(256)
pconv_hmma(const float* __restrict__ feat, const int* __restrict__ inds,
           const float* __restrict__ guid, const float* __restrict__ wn,
           float* __restrict__ out) {
    // Per-warp staging. Row stride 40 words (40 mod 32 = 8): bank = (8k + c) & 31,
    // bijective over every fragment's 32 lanes -> conflict-free STS and LDS.
    // Reused (stride 36) for the D transpose before the coalesced store.
    __shared__ uint32_t s_gf[8][16 * 40];

    const int warp = threadIdx.x >> 5;
    const int lane = threadIdx.x & 31;
    const int point = blockIdx.x * 8 + warp;       // grid covers 160000 exactly
    uint32_t* sg = s_gf[warp];

    // ---- neighbor indices (16 ints, lanes 0..15) ----
    int myidx = 0;
    if (lane < 16) myidx = __ldg(inds + point * 16 + lane);

    // ---- B operand loads issued early (raises MLP; used after gather) ----
    // b(q,j): k = (lane&3) + 4j + 8q, m = lane>>2.
    // Word index 8*(lane&3) + (lane>>2) + 32j + 64q: each LDG covers one
    // permuted-but-contiguous 128B line -> coalesced.
    const float* wp = wn + (size_t)point * 128;
    const int widx = 8 * (lane & 3) + (lane >> 2);
    float wraw[2][2];
    #pragma unroll
    for (int q = 0; q < 2; q++)
        #pragma unroll
        for (int j = 0; j < 2; j++)
            wraw[q][j] = __ldg(wp + widx + 32 * j + 64 * q);

    // ---- guidance, coalesced: lane j holds guid[point*64 + j] ----
    const float g0 = __ldg(guid + point * 64 + lane);
    const float g1 = __ldg(guid + point * 64 + 32 + lane);
    const int h = lane >> 3;                        // head of this lane's channel

    const float* fb = feat + ((point >= NPERB) ? NPERB * 32 : 0);

    // ---- gather + guidance multiply + tf32 round + stage gf[k][c] ----
    #pragma unroll
    for (int k = 0; k < 16; k++) {
        const int ik = __shfl_sync(FULLMASK, myidx, k);
        const float fv = __ldg(fb + ik * 32 + lane);
        const float gv = (k < 8) ? __shfl_sync(FULLMASK, g0, k * 4 + h)
                                 : __shfl_sync(FULLMASK, g1, (k - 8) * 4 + h);
        sg[k * 40 + lane] = tf32_rn(fv * gv);
    }
    __syncwarp();

    // ---- B fragments: tf32 round only (single-pass precision) ----
    uint32_t B[2][2];
    #pragma unroll
    for (int q = 0; q < 2; q++)
        #pragma unroll
        for (int j = 0; j < 2; j++)
            B[q][j] = tf32_rn(wraw[q][j]);

    float d[2][4];
    #pragma unroll
    for (int t = 0; t < 2; t++)
        #pragma unroll
        for (int i = 0; i < 4; i++) d[t][i] = 0.0f;

    // ---- 2 M-tiles x 2 K-halves ----
    #pragma unroll
    for (int t = 0; t < 2; t++) {
        #pragma unroll
        for (int q = 0; q < 2; q++) {
            uint32_t A[4];
            #pragma unroll
            for (int i = 0; i < 4; i++) {
                const int k = (lane & 3) + 4 * (i >> 1) + 8 * q;
                const int c = (lane >> 2) + 8 * (i & 1) + 16 * t;
                A[i] = sg[k * 40 + c];
            }
            mma8(d[t], A, B[q][0], B[q][1]);
        }
    }
    __syncwarp();   // all A-frag reads complete before sg is overwritten

    // ---- D -> smem transpose (stride 36: bank = (4m + c)&31, conflict-free) ----
    // d[t][i]: m = (lane&3)*2 + (i&1), c = (lane>>2) + 8*(i>>1) + 16*t.
    #pragma unroll
    for (int t = 0; t < 2; t++)
        #pragma unroll
        for (int i = 0; i < 4; i++) {
            const int m = (lane & 3) * 2 + (i & 1);
            const int c = (lane >> 2) + 8 * (i >> 1) + 16 * t;
            sg[m * 36 + c] = __float_as_uint(d[t][i]);
        }
    __syncwarp();

    // ---- coalesced store: out[point, m*32 + c] ----
    float* op = out + (size_t)point * 256;
    #pragma unroll
    for (int m = 0; m < 8; m++)
        op[m * 32 + lane] = __uint_as_float(sg[m * 36 + lane]);
}

extern "C" void kernel_launch(void* const* d_in, const int* in_sizes, int n_in,
                              void* d_out, int out_size) {
    const float* feat = (const float*)d_in[0];   // [B,N,C]
    const int*   inds = (const int*)  d_in[1];   // [B,N,K]
    const float* guid = (const float*)d_in[2];   // [B,N,K,H]
    const float* wn   = (const float*)d_in[3];   // [B,N,K,M]
    float* out = (float*)d_out;                  // [B,N,M*C]

    pconv_hmma<<<20000, 256>>>(feat, inds, guid, wn, out);
}